// round 14
// baseline (speedup 1.0000x reference)
#include <cuda_runtime.h>
#include <cstdint>

#define DIM    256
#define HW     1024
#define NPIX   65536
#define NCODE  1024
#define NCHUNK 8          // 1024 codes / 128 per chunk

// quantization scales (emb kaiming-uniform bound sqrt(3/256); z ~ N(0,1))
#define E_BOUND 0.10825317547305482f
#define SC_E    (127.0f / E_BOUND)
#define SC_Z    (127.0f / 4.5f)
#define KSC     (-2.0f * (4.5f / 127.0f) * (E_BOUND / 127.0f))   // -2/(SC_Z*SC_E)

// ------------------------- device globals (scratch) -------------------------
__device__ float   g_bias[NCODE];        // sum(e_n^2), fp64->fp32
__device__ int     g_cand[NPIX * 8];     // top-8 approx candidates
__device__ int8_t  g_embq[NCODE * DIM];  // int8 codebook

// ------------------------- PTX helpers (baseline ISA only) ------------------
__device__ __forceinline__ uint32_t smem_u32(const void* p) {
    uint32_t a;
    asm("{ .reg .u64 t; cvta.to.shared.u64 t, %1; cvt.u32.u64 %0, t; }"
        : "=r"(a) : "l"(p));
    return a;
}
__device__ __forceinline__ void ldsm4(uint32_t& r0, uint32_t& r1, uint32_t& r2,
                                      uint32_t& r3, uint32_t addr) {
    asm volatile("ldmatrix.sync.aligned.m8n8.x4.shared.b16 {%0,%1,%2,%3}, [%4];"
                 : "=r"(r0), "=r"(r1), "=r"(r2), "=r"(r3) : "r"(addr));
}
__device__ __forceinline__ void mma16832(int* d, const uint32_t* a,
                                         uint32_t b0, uint32_t b1) {
    asm volatile("mma.sync.aligned.m16n8k32.row.col.s32.s8.s8.s32 "
                 "{%0,%1,%2,%3}, {%4,%5,%6,%7}, {%8,%9}, {%0,%1,%2,%3};"
                 : "+r"(d[0]), "+r"(d[1]), "+r"(d[2]), "+r"(d[3])
                 : "r"(a[0]), "r"(a[1]), "r"(a[2]), "r"(a[3]), "r"(b0), "r"(b1));
}
#define CP_ASYNC16(dst, src) \
    asm volatile("cp.async.cg.shared.global [%0], [%1], 16;" :: "r"(dst), "l"(src))
#define CP_COMMIT() asm volatile("cp.async.commit_group;" ::: "memory")
#define CP_WAIT0()  asm volatile("cp.async.wait_group 0;" ::: "memory")

__device__ __forceinline__ uint32_t pack4(float a, float b, float c, float d,
                                          float s) {
    int x0 = max(-127, min(127, __float2int_rn(a * s)));
    int x1 = max(-127, min(127, __float2int_rn(b * s)));
    int x2 = max(-127, min(127, __float2int_rn(c * s)));
    int x3 = max(-127, min(127, __float2int_rn(d * s)));
    return (uint32_t)(x0 & 255) | ((uint32_t)(x1 & 255) << 8)
         | ((uint32_t)(x2 & 255) << 16) | ((uint32_t)(x3 & 255) << 24);
}

// ---------------------------------------------------------------------------
// Kernel 1 (prep): g_bias (fp64 exact) + int8 codebook. Warp per row.
// ---------------------------------------------------------------------------
__global__ void vq_prep(const float* __restrict__ emb) {
    int n   = blockIdx.x * 8 + (threadIdx.x >> 5);
    int lid = threadIdx.x & 31;
    const float4* row = reinterpret_cast<const float4*>(emb + (size_t)n * DIM);
    float4 u = __ldg(row + lid * 2);
    float4 t = __ldg(row + lid * 2 + 1);
    double s = (double)u.x * u.x + (double)u.y * u.y + (double)u.z * u.z + (double)u.w * u.w
             + (double)t.x * t.x + (double)t.y * t.y + (double)t.z * t.z + (double)t.w * t.w;
#pragma unroll
    for (int off = 16; off; off >>= 1) s += __shfl_xor_sync(0xffffffffu, s, off);
    if (lid == 0) g_bias[n] = (float)s;
    uint2 o;
    o.x = pack4(u.x, u.y, u.z, u.w, SC_E);
    o.y = pack4(t.x, t.y, t.z, t.w, SC_E);
    *reinterpret_cast<uint2*>(&g_embq[(size_t)n * DIM + lid * 8]) = o;
}

// ---------------------------------------------------------------------------
// Kernel 2: int8 mma.sync GEMM + top-8 shortlist. 512 threads / 16 warps.
// A_p (||z||^2) is per-pixel constant -> dropped from the ranking entirely.
// Packed value: bits(64 + B_n - 2s*dot) | id  (always in (16,128) > 0).
// ---------------------------------------------------------------------------
#define SM_A   0                      // 128 x 256 int8 = 32 KB
#define SM_B0  32768
#define SM_B1  65536
#define SM_TOT 98304

#define ROWOFF8(row, kc) ((row) * 256 + ((((kc) ^ ((row) & 7))) << 4))

__device__ __forceinline__ void prefetch_b(uint32_t bbuf, int nbase, int t) {
    const char* src = (const char*)g_embq + (size_t)nbase * 256;
#pragma unroll
    for (int i = 0; i < 4; ++i) {
        int idx = t + i * 512;       // 0..2047
        int n = idx >> 4, c = idx & 15;
        CP_ASYNC16(bbuf + ROWOFF8(n, c), src + n * 256 + c * 16);
    }
}

extern __shared__ char smem[];

__global__ __launch_bounds__(512, 1)
void vq_gemm(const float* __restrict__ z) {
    const uint32_t sb = smem_u32(smem);
    const int t = threadIdx.x, wid = t >> 5, lane = t & 31;
    const int wm = wid & 3, wn = wid >> 2;           // 4 x 4 warp grid
    const int b = blockIdx.x >> 3, q0 = (blockIdx.x & 7) * 128;

    // ---- stage A (fp32 -> int8, swizzled); no norm pass needed ----
    {
        const int m = t & 127, kq = t >> 7;          // kq 0..3 -> 64 dims each
        const float* zb = z + (size_t)b * DIM * HW + q0 + m;
#pragma unroll
        for (int ch = 0; ch < 4; ++ch) {
            int k0 = kq * 64 + ch * 16;
            float vv[16];
#pragma unroll
            for (int j = 0; j < 16; ++j)
                vv[j] = zb[(size_t)(k0 + j) * HW];
            uint4 w;
            w.x = pack4(vv[0],  vv[1],  vv[2],  vv[3],  SC_Z);
            w.y = pack4(vv[4],  vv[5],  vv[6],  vv[7],  SC_Z);
            w.z = pack4(vv[8],  vv[9],  vv[10], vv[11], SC_Z);
            w.w = pack4(vv[12], vv[13], vv[14], vv[15], SC_Z);
            *reinterpret_cast<uint4*>(smem + SM_A + ROWOFF8(m, kq * 4 + ch)) = w;
        }
    }

    prefetch_b(sb + SM_B0, 0, t);
    CP_COMMIT();
    CP_WAIT0();
    __syncthreads();

    const int lrow  = (lane & 7) + ((lane >> 3) & 1) * 8;
    const int kcsel = lane >> 4;
    const int rowA0 = wm * 32 + lrow;
    const int rowB0 = wn * 32 + lrow;
    const uint32_t abase = sb + SM_A;

    uint32_t cv[4][4];
#pragma unroll
    for (int r = 0; r < 4; ++r)
#pragma unroll
        for (int j = 0; j < 4; ++j) cv[r][j] = 0xFFFFFFFFu;

    for (int nt = 0; nt < NCHUNK; ++nt) {
        if (nt + 1 < NCHUNK) {
            prefetch_b(sb + (((nt + 1) & 1) ? SM_B1 : SM_B0), (nt + 1) * 128, t);
            CP_COMMIT();
        }
        const uint32_t bbuf = sb + ((nt & 1) ? SM_B1 : SM_B0);

        int acc[2][4][4];
#pragma unroll
        for (int mt = 0; mt < 2; ++mt)
#pragma unroll
            for (int n2 = 0; n2 < 4; ++n2)
#pragma unroll
                for (int j = 0; j < 4; ++j) acc[mt][n2][j] = 0;

        uint32_t afrag[2][2][4], bfrag[2][2][4];
#define LOAD_KS(ks, buf)                                                        \
        {                                                                       \
            const int kc_ = 2 * (ks) + kcsel;                                   \
            ldsm4(afrag[buf][0][0], afrag[buf][0][1], afrag[buf][0][2],         \
                  afrag[buf][0][3], abase + ROWOFF8(rowA0, kc_));               \
            ldsm4(afrag[buf][1][0], afrag[buf][1][1], afrag[buf][1][2],         \
                  afrag[buf][1][3], abase + ROWOFF8(rowA0 + 16, kc_));          \
            ldsm4(bfrag[buf][0][0], bfrag[buf][0][1], bfrag[buf][0][2],         \
                  bfrag[buf][0][3], bbuf + ROWOFF8(rowB0, kc_));                \
            ldsm4(bfrag[buf][1][0], bfrag[buf][1][1], bfrag[buf][1][2],         \
                  bfrag[buf][1][3], bbuf + ROWOFF8(rowB0 + 16, kc_));           \
        }
        LOAD_KS(0, 0)
#pragma unroll
        for (int ks = 0; ks < 8; ++ks) {             // 256 dims / 32 per mma
            if (ks < 7) LOAD_KS(ks + 1, (ks + 1) & 1)
            const int cur = ks & 1;
#pragma unroll
            for (int g = 0; g < 2; ++g)
#pragma unroll
                for (int mt = 0; mt < 2; ++mt) {
                    mma16832(acc[mt][g * 2 + 0], afrag[cur][mt],
                             bfrag[cur][g][0], bfrag[cur][g][2]);
                    mma16832(acc[mt][g * 2 + 1], afrag[cur][mt],
                             bfrag[cur][g][1], bfrag[cur][g][3]);
                }
        }
#undef LOAD_KS

        // ---- epilogue: pack (64 + B - 2s*dot, id); A_p cancels in ranking --
        const int nb0 = nt * 128 + wn * 32 + (lane & 3) * 2;
        float bias2[8];
#pragma unroll
        for (int n2 = 0; n2 < 4; ++n2) {
            bias2[n2 * 2 + 0] = __ldg(&g_bias[nb0 + n2 * 8 + 0]);
            bias2[n2 * 2 + 1] = __ldg(&g_bias[nb0 + n2 * 8 + 1]);
        }
#pragma unroll
        for (int mt = 0; mt < 2; ++mt)
#pragma unroll
            for (int h = 0; h < 2; ++h) {
                const int rr = mt * 2 + h;
#pragma unroll
                for (int n2 = 0; n2 < 4; ++n2)
#pragma unroll
                    for (int bb = 0; bb < 2; ++bb) {
                        float s2 = fmaf(KSC, (float)acc[mt][n2][h * 2 + bb],
                                        bias2[n2 * 2 + bb]) + 64.0f;
                        uint32_t u = (__float_as_uint(s2) & 0xFFFFFC00u)
                                   | (uint32_t)(nb0 + n2 * 8 + bb);
                        if (u < cv[rr][3]) {
                            cv[rr][3] = u;
#pragma unroll
                            for (int v = 3; v > 0; --v) {
                                bool sw = cv[rr][v] < cv[rr][v - 1];
                                uint32_t tv = cv[rr][v - 1];
                                cv[rr][v - 1] = sw ? cv[rr][v] : cv[rr][v - 1];
                                cv[rr][v]     = sw ? tv : cv[rr][v];
                            }
                        }
                    }
            }

        CP_WAIT0();
        __syncthreads();
    }

    // ---- merge 64 packed candidates/pixel -> top-8 (scratch in B0/B1) ----
    uint32_t* mv = reinterpret_cast<uint32_t*>(smem + SM_B0);
    const int owner = wn * 4 + (lane & 3);           // 0..15
#pragma unroll
    for (int rr = 0; rr < 4; ++rr) {
        int m = wm * 32 + (rr >> 1) * 16 + (rr & 1) * 8 + (lane >> 2);
#pragma unroll
        for (int j = 0; j < 4; ++j)
            mv[m * 65 + owner * 4 + j] = cv[rr][j];
    }
    __syncthreads();
    if (t < 128) {
        uint32_t v8[8];
#pragma unroll
        for (int j = 0; j < 8; ++j) v8[j] = 0xFFFFFFFFu;
        const uint32_t* vr = mv + t * 65;
#pragma unroll 4
        for (int j = 0; j < 64; ++j) {
            uint32_t u = vr[j];
            if (u < v8[7]) {
                v8[7] = u;
#pragma unroll
                for (int v = 7; v > 0; --v) {
                    bool sw = v8[v] < v8[v - 1];
                    uint32_t tv = v8[v - 1];
                    v8[v - 1] = sw ? v8[v] : v8[v - 1];
                    v8[v]     = sw ? tv : v8[v];
                }
            }
        }
        int p = b * HW + q0 + t;
        int4* dst = reinterpret_cast<int4*>(&g_cand[p * 8]);
        dst[0] = make_int4(v8[0] & 1023, v8[1] & 1023, v8[2] & 1023, v8[3] & 1023);
        dst[1] = make_int4(v8[4] & 1023, v8[5] & 1023, v8[6] & 1023, v8[7] & 1023);
    }
}

// ---------------------------------------------------------------------------
// Kernel 3: exact fp32 rescore (smem-staged, R13-proven structure) + fused
// z_q gather. A_p computed here from staged zs via exact-product compensated
// fp32 (Neumaier + FMA residuals + TwoSum combine; deterministic order).
// The d-computation FMA sequence stays bit-frozen (rounds 2..13 contract).
// ---------------------------------------------------------------------------
#define RS_ZS   0
#define RS_EB   32768
#define RS_IDS  (RS_EB + 35328)
#define RS_DV   (RS_IDS + 1024)
#define RS_DI   (RS_DV + 1024)
#define RS_SP   (RS_DI + 1024)
#define RS_CP   (RS_SP + 512)
#define RS_AS   (RS_CP + 512)
#define RS_FIN  (RS_AS + 128)
#define RS_TOT  (RS_FIN + 128)
#define EPITCH  276                   // floats; 16B-aligned, conflict-free

__global__ __launch_bounds__(256)
void vq_rescore(const float* __restrict__ z, const float* __restrict__ emb,
                float* __restrict__ fo, int* __restrict__ io,
                float* __restrict__ zq) {
    float* zs  = reinterpret_cast<float*>(smem + RS_ZS);    // [k][m] pitch 32
    float* ef  = reinterpret_cast<float*>(smem + RS_EB);    // [32][EPITCH]
    int*   ids = reinterpret_cast<int*>(smem + RS_IDS);
    float* dv  = reinterpret_cast<float*>(smem + RS_DV);
    int*   di  = reinterpret_cast<int*>(smem + RS_DI);
    float* sp  = reinterpret_cast<float*>(smem + RS_SP);    // [4][32]
    float* cp  = reinterpret_cast<float*>(smem + RS_CP);    // [4][32]
    float* Asm = reinterpret_cast<float*>(smem + RS_AS);    // [32]
    int*   fin = reinterpret_cast<int*>(smem + RS_FIN);     // [32]
    const int t = threadIdx.x, wid = t >> 5, lane = t & 31;
    const int p0 = blockIdx.x * 32;
    const int b = p0 >> 10, q0 = p0 & 1023;
    {
        int m = t & 31, kb = t >> 5;
        const float* zb = z + (size_t)b * DIM * HW + q0 + m;
#pragma unroll 8
        for (int i = 0; i < 32; ++i) {
            int k = kb + i * 8;
            zs[k * 32 + m] = zb[(size_t)k * HW];
        }
    }
    ids[t] = g_cand[p0 * 8 + t];
    __syncthreads();

    // ---- A_p: exact-product compensated fp32, 4 quarters per pixel ----
    if (t < 128) {
        int m = t & 31, q = t >> 5;
        float s = 0.f, comp = 0.f, rs = 0.f;
        for (int i = 0; i < 64; ++i) {
            float v = zs[(q * 64 + i) * 32 + m];
            float p = v * v;
            float r = fmaf(v, v, -p);               // exact residual
            float tt = s + p;
            comp += (fabsf(s) >= fabsf(p)) ? ((s - tt) + p) : ((p - tt) + s);
            s = tt;
            rs += r;
        }
        sp[q * 32 + m] = s;
        cp[q * 32 + m] = comp + rs;
    }
    __syncthreads();
    if (t < 32) {
        float s = 0.f, c = 0.f;
#pragma unroll
        for (int q = 0; q < 4; ++q) {               // TwoSum chain
            float bq = sp[q * 32 + t];
            float tt = s + bq;
            float bb = tt - s;
            c += (s - (tt - bb)) + (bq - bb);
            s = tt;
            c += cp[q * 32 + t];
        }
        Asm[t] = s + c;
    }
    __syncthreads();

    const float4* e4g = reinterpret_cast<const float4*>(emb);
    for (int c = 0; c < 8; ++c) {
        {   // coalesced load: 8 threads per row, 32 rows of candidate c
            int r = t >> 3, cc = t & 7;
            const float4* src = e4g + (size_t)ids[r * 8 + c] * 64;
#pragma unroll
            for (int i = 0; i < 8; ++i) {
                float4 v = __ldg(src + cc + i * 8);
                *reinterpret_cast<float4*>(&ef[r * EPITCH + (cc + i * 8) * 4]) = v;
            }
        }
        __syncthreads();
        if (wid == c) {
            const int m = lane;
            const int n = ids[m * 8 + c];
            const float Ap = Asm[m], Bn = __ldg(&g_bias[n]);
            const float* er = ef + m * EPITCH;
            const float* zr = zs + m;
            float a0 = 0.f, a1 = 0.f, a2 = 0.f, a3 = 0.f;
#pragma unroll 8
            for (int k4 = 0; k4 < 64; ++k4) {       // bit-frozen serial 4-chain
                float4 e = *reinterpret_cast<const float4*>(&er[k4 * 4]);
                a0 = fmaf(zr[(k4 * 4 + 0) * 32], e.x, a0);
                a1 = fmaf(zr[(k4 * 4 + 1) * 32], e.y, a1);
                a2 = fmaf(zr[(k4 * 4 + 2) * 32], e.z, a2);
                a3 = fmaf(zr[(k4 * 4 + 3) * 32], e.w, a3);
            }
            float dot = (a0 + a1) + (a2 + a3);
            float d = __fadd_rn(__fadd_rn(Ap, Bn), -2.0f * dot);
            dv[c * 32 + m] = d; di[c * 32 + m] = n;
        }
        __syncthreads();   // compute done before ebuf overwritten
    }

    if (t < 32) {          // min over (value, index), lowest index on ties
        float bv = dv[t]; int bi = di[t];
#pragma unroll
        for (int c = 1; c < 8; ++c) {
            float ov = dv[c * 32 + t]; int oi = di[c * 32 + t];
            if (ov < bv || (ov == bv && oi < bi)) { bv = ov; bi = oi; }
        }
        int p = p0 + t;
        fin[t] = bi;
        if (fo) fo[p] = (float)bi;
        if (io) io[p] = bi;
    }

    // ---- fused gather (verbatim R12 logic; ef reused as transpose buf) ----
    if (zq) {
        __syncthreads();
        float* zsx = ef;                            // 32 x 257 floats
        {
            int r = t >> 3, cc = t & 7;
            const float4* src = e4g + (size_t)fin[r] * 64;
#pragma unroll
            for (int i = 0; i < 8; ++i) {
                float4 v = __ldg(src + cc + i * 8);
                int d = (cc + i * 8) * 4;
                zsx[r * 257 + d + 0] = v.x;
                zsx[r * 257 + d + 1] = v.y;
                zsx[r * 257 + d + 2] = v.z;
                zsx[r * 257 + d + 3] = v.w;
            }
        }
        __syncthreads();
        {
            int q = t & 31, w = t >> 5;
            float* o = zq + (size_t)b * DIM * HW + q0 + q;
#pragma unroll 8
            for (int i = 0; i < 32; ++i) {
                int d = w * 32 + i;
                o[(size_t)d * HW] = zsx[q * 257 + d];
            }
        }
    }
}

// ---------------------------------------------------------------------------
extern "C" void kernel_launch(void* const* d_in, const int* in_sizes, int n_in,
                              void* d_out, int out_size) {
    const float* z   = (const float*)d_in[0];
    const float* emb = (const float*)d_in[1];
    if (n_in >= 2 && in_sizes[0] == NCODE * DIM) {
        emb = (const float*)d_in[0]; z = (const float*)d_in[1];
    } else if (n_in >= 2 && in_sizes[1] == NCODE * DIM) {
        z = (const float*)d_in[0]; emb = (const float*)d_in[1];
    }

    const int ZQ = NPIX * DIM;
    float* fo = nullptr; int* io = nullptr; float* zq = nullptr;
    if (out_size == NPIX)      { io = (int*)d_out; }
    else if (out_size == ZQ)   { zq = (float*)d_out; }
    else                       { fo = (float*)d_out; zq = (float*)d_out + NPIX; }

    cudaFuncSetAttribute(vq_gemm, cudaFuncAttributeMaxDynamicSharedMemorySize, SM_TOT);
    cudaFuncSetAttribute(vq_rescore, cudaFuncAttributeMaxDynamicSharedMemorySize, RS_TOT);

    vq_prep<<<128, 256>>>(emb);
    vq_gemm<<<NPIX / 128, 512, SM_TOT>>>(z);
    vq_rescore<<<NPIX / 32, 256, RS_TOT>>>(z, emb, fo, io, zq);
}

// round 15
// speedup vs baseline: 1.2684x; 1.2684x over previous
#include <cuda_runtime.h>
#include <cuda_bf16.h>
#include <cstdint>

#define DIM    256
#define HW     1024
#define NPIX   65536
#define NCODE  1024
#define NCHUNK 8          // 1024 codes / 128 per chunk

// ------------------------- device globals (scratch) -------------------------
__device__ float         g_bias[NCODE];        // sum(e_n^2), fp64->fp32
__device__ float         g_A[NPIX];            // sum(z_p^2), fp64->fp32
__device__ int           g_cand[NPIX * 4];     // top-4 approx candidates
__device__ int           g_idx[NPIX];          // final indices
__device__ __nv_bfloat16 g_embh[NCODE * DIM];  // bf16 codebook

// ------------------------- PTX helpers (baseline ISA only) ------------------
__device__ __forceinline__ uint32_t smem_u32(const void* p) {
    uint32_t a;
    asm("{ .reg .u64 t; cvta.to.shared.u64 t, %1; cvt.u32.u64 %0, t; }"
        : "=r"(a) : "l"(p));
    return a;
}
__device__ __forceinline__ void ldsm4(uint32_t& r0, uint32_t& r1, uint32_t& r2,
                                      uint32_t& r3, uint32_t addr) {
    asm volatile("ldmatrix.sync.aligned.m8n8.x4.shared.b16 {%0,%1,%2,%3}, [%4];"
                 : "=r"(r0), "=r"(r1), "=r"(r2), "=r"(r3) : "r"(addr));
}
__device__ __forceinline__ void mma16816(float* d, const uint32_t* a,
                                         uint32_t b0, uint32_t b1) {
    asm volatile("mma.sync.aligned.m16n8k16.row.col.f32.bf16.bf16.f32 "
                 "{%0,%1,%2,%3}, {%4,%5,%6,%7}, {%8,%9}, {%0,%1,%2,%3};"
                 : "+f"(d[0]), "+f"(d[1]), "+f"(d[2]), "+f"(d[3])
                 : "r"(a[0]), "r"(a[1]), "r"(a[2]), "r"(a[3]), "r"(b0), "r"(b1));
}
#define CP_ASYNC16(dst, src) \
    asm volatile("cp.async.cg.shared.global [%0], [%1], 16;" :: "r"(dst), "l"(src))
#define CP_COMMIT() asm volatile("cp.async.commit_group;" ::: "memory")
#define CP_WAIT0()  asm volatile("cp.async.wait_group 0;" ::: "memory")

// ---------------------------------------------------------------------------
// no-op kernel: launch-order padding so ncu (-s 5 -c 1) lands on vq_gemm.
// ---------------------------------------------------------------------------
__global__ void vq_nop() {}

// ---------------------------------------------------------------------------
// Kernel 1 (prep): g_bias (fp64 exact, bit-identical order to prior rounds)
// + bf16 codebook. grid=128, block=256: warp per codebook row.
// ---------------------------------------------------------------------------
__global__ void vq_prep(const float* __restrict__ emb) {
    int n   = blockIdx.x * 8 + (threadIdx.x >> 5);
    int lid = threadIdx.x & 31;
    const float4* row = reinterpret_cast<const float4*>(emb + (size_t)n * DIM);
    float4 u = __ldg(row + lid * 2);
    float4 t = __ldg(row + lid * 2 + 1);
    double s = (double)u.x * u.x + (double)u.y * u.y + (double)u.z * u.z + (double)u.w * u.w
             + (double)t.x * t.x + (double)t.y * t.y + (double)t.z * t.z + (double)t.w * t.w;
#pragma unroll
    for (int off = 16; off; off >>= 1) s += __shfl_xor_sync(0xffffffffu, s, off);
    if (lid == 0) g_bias[n] = (float)s;
    __nv_bfloat162 h0 = __floats2bfloat162_rn(u.x, u.y);
    __nv_bfloat162 h1 = __floats2bfloat162_rn(u.z, u.w);
    __nv_bfloat162 h2 = __floats2bfloat162_rn(t.x, t.y);
    __nv_bfloat162 h3 = __floats2bfloat162_rn(t.z, t.w);
    uint4 o;
    o.x = *reinterpret_cast<uint32_t*>(&h0); o.y = *reinterpret_cast<uint32_t*>(&h1);
    o.z = *reinterpret_cast<uint32_t*>(&h2); o.w = *reinterpret_cast<uint32_t*>(&h3);
    *reinterpret_cast<uint4*>(&g_embh[(size_t)n * DIM + lid * 8]) = o;
}

// ---------------------------------------------------------------------------
// Kernel 2: bf16 mma.sync GEMM + top-4 shortlist (verbatim from R10 -- the
// proven 272-us configuration). 512 threads / 16 warps, 4x4 warp grid.
// ---------------------------------------------------------------------------
#define SM_A   0
#define SM_B0  65536
#define SM_B1  131072
#define SM_AP  196608                 // double[512]
#define SM_AF  200704                 // float[128]
#define SM_TOT 201344

#define ROWOFF(row, kc) ((row) * 512 + (((kc) ^ ((row) & 7)) << 4))

__device__ __forceinline__ void prefetch_b(uint32_t bbuf, int nbase, int t) {
    const char* src = (const char*)g_embh + (size_t)nbase * 512;
#pragma unroll
    for (int i = 0; i < 8; ++i) {
        int idx = t + i * 512;       // 0..4095
        int n = idx >> 5, c = idx & 31;
        CP_ASYNC16(bbuf + ROWOFF(n, c), src + n * 512 + c * 16);
    }
}

extern __shared__ char smem[];

__global__ __launch_bounds__(512, 1)
void vq_gemm(const float* __restrict__ z) {
    const uint32_t sb = smem_u32(smem);
    const int t = threadIdx.x, wid = t >> 5, lane = t & 31;
    const int wm = wid & 3, wn = wid >> 2;           // 4 x 4 warp grid
    const int b = blockIdx.x >> 3, q0 = (blockIdx.x & 7) * 128;

    // ---- stage A (fp32 -> bf16, swizzled) + fp64 ||z||^2 partials ----
    {
        const int m = t & 127, kq = t >> 7;          // kq 0..3 -> 64 dims each
        const float* zb = z + (size_t)b * DIM * HW + q0 + m;
        double s = 0.0;
#pragma unroll
        for (int ch = 0; ch < 8; ++ch) {
            int k0 = kq * 64 + ch * 8;
            float vv[8];
#pragma unroll
            for (int j = 0; j < 8; ++j) {
                vv[j] = zb[(size_t)(k0 + j) * HW];
                s += (double)vv[j] * vv[j];
            }
            uint4 w;
            __nv_bfloat162 h0 = __floats2bfloat162_rn(vv[0], vv[1]);
            __nv_bfloat162 h1 = __floats2bfloat162_rn(vv[2], vv[3]);
            __nv_bfloat162 h2 = __floats2bfloat162_rn(vv[4], vv[5]);
            __nv_bfloat162 h3 = __floats2bfloat162_rn(vv[6], vv[7]);
            w.x = *reinterpret_cast<uint32_t*>(&h0); w.y = *reinterpret_cast<uint32_t*>(&h1);
            w.z = *reinterpret_cast<uint32_t*>(&h2); w.w = *reinterpret_cast<uint32_t*>(&h3);
            *reinterpret_cast<uint4*>(smem + SM_A + ROWOFF(m, k0 >> 3)) = w;
        }
        reinterpret_cast<double*>(smem + SM_AP)[t] = s;
    }

    prefetch_b(sb + SM_B0, 0, t);
    CP_COMMIT();
    CP_WAIT0();
    __syncthreads();

    if (t < 128) {
        const double* ap = reinterpret_cast<const double*>(smem + SM_AP);
        float Af = (float)(ap[t] + ap[t + 128] + ap[t + 256] + ap[t + 384]);
        g_A[b * HW + q0 + t] = Af;
        reinterpret_cast<float*>(smem + SM_AF)[t] = Af;
    }
    __syncthreads();

    const int lrow  = (lane & 7) + ((lane >> 3) & 1) * 8;
    const int kcsel = lane >> 4;
    const int rowA0 = wm * 32 + lrow;
    const int rowB0 = wn * 32 + lrow;
    const uint32_t abase = sb + SM_A;

    float Arow[4];
#pragma unroll
    for (int rr = 0; rr < 4; ++rr) {
        int m = wm * 32 + (rr >> 1) * 16 + (rr & 1) * 8 + (lane >> 2);
        Arow[rr] = reinterpret_cast<const float*>(smem + SM_AF)[m];
    }

    uint32_t cv[4][4];
#pragma unroll
    for (int r = 0; r < 4; ++r)
#pragma unroll
        for (int j = 0; j < 4; ++j) cv[r][j] = 0xFFFFFFFFu;

    for (int nt = 0; nt < NCHUNK; ++nt) {
        if (nt + 1 < NCHUNK) {
            prefetch_b(sb + (((nt + 1) & 1) ? SM_B1 : SM_B0), (nt + 1) * 128, t);
            CP_COMMIT();
        }
        const uint32_t bbuf = sb + ((nt & 1) ? SM_B1 : SM_B0);

        float acc[2][4][4];
#pragma unroll
        for (int mt = 0; mt < 2; ++mt)
#pragma unroll
            for (int n2 = 0; n2 < 4; ++n2)
#pragma unroll
                for (int j = 0; j < 4; ++j) acc[mt][n2][j] = 0.f;

        uint32_t afrag[2][2][4], bfrag[2][2][4];
#define LOAD_KS(ks, buf)                                                        \
        {                                                                       \
            const int kc_ = 2 * (ks) + kcsel;                                   \
            ldsm4(afrag[buf][0][0], afrag[buf][0][1], afrag[buf][0][2],         \
                  afrag[buf][0][3], abase + ROWOFF(rowA0, kc_));                \
            ldsm4(afrag[buf][1][0], afrag[buf][1][1], afrag[buf][1][2],         \
                  afrag[buf][1][3], abase + ROWOFF(rowA0 + 16, kc_));           \
            ldsm4(bfrag[buf][0][0], bfrag[buf][0][1], bfrag[buf][0][2],         \
                  bfrag[buf][0][3], bbuf + ROWOFF(rowB0, kc_));                 \
            ldsm4(bfrag[buf][1][0], bfrag[buf][1][1], bfrag[buf][1][2],         \
                  bfrag[buf][1][3], bbuf + ROWOFF(rowB0 + 16, kc_));            \
        }
        LOAD_KS(0, 0)
#pragma unroll
        for (int ks = 0; ks < 16; ++ks) {
            if (ks < 15) LOAD_KS(ks + 1, (ks + 1) & 1)
            const int cur = ks & 1;
#pragma unroll
            for (int g = 0; g < 2; ++g)
#pragma unroll
                for (int mt = 0; mt < 2; ++mt) {
                    mma16816(acc[mt][g * 2 + 0], afrag[cur][mt],
                             bfrag[cur][g][0], bfrag[cur][g][2]);
                    mma16816(acc[mt][g * 2 + 1], afrag[cur][mt],
                             bfrag[cur][g][1], bfrag[cur][g][3]);
                }
        }
#undef LOAD_KS

        const int nb0 = nt * 128 + wn * 32 + (lane & 3) * 2;
        float bias2[8];
#pragma unroll
        for (int n2 = 0; n2 < 4; ++n2) {
            bias2[n2 * 2 + 0] = __ldg(&g_bias[nb0 + n2 * 8 + 0]);
            bias2[n2 * 2 + 1] = __ldg(&g_bias[nb0 + n2 * 8 + 1]);
        }
#pragma unroll
        for (int mt = 0; mt < 2; ++mt)
#pragma unroll
            for (int h = 0; h < 2; ++h) {
                const int rr = mt * 2 + h;
#pragma unroll
                for (int n2 = 0; n2 < 4; ++n2)
#pragma unroll
                    for (int bb = 0; bb < 2; ++bb) {
                        float s2 = fmaf(-2.f, acc[mt][n2][h * 2 + bb],
                                        bias2[n2 * 2 + bb]) + Arow[rr];
                        uint32_t u = (__float_as_uint(s2) & 0xFFFFFC00u)
                                   | (uint32_t)(nb0 + n2 * 8 + bb);
                        if (u < cv[rr][3]) {
                            cv[rr][3] = u;
#pragma unroll
                            for (int v = 3; v > 0; --v) {
                                bool sw = cv[rr][v] < cv[rr][v - 1];
                                uint32_t tv = cv[rr][v - 1];
                                cv[rr][v - 1] = sw ? cv[rr][v] : cv[rr][v - 1];
                                cv[rr][v]     = sw ? tv : cv[rr][v];
                            }
                        }
                    }
            }

        CP_WAIT0();
        __syncthreads();
    }

    // ---- merge 64 packed candidates/pixel -> top-4 (scratch in B0, pad 65) --
    uint32_t* mv = reinterpret_cast<uint32_t*>(smem + SM_B0);
    const int owner = wn * 4 + (lane & 3);           // 0..15
#pragma unroll
    for (int rr = 0; rr < 4; ++rr) {
        int m = wm * 32 + (rr >> 1) * 16 + (rr & 1) * 8 + (lane >> 2);
#pragma unroll
        for (int j = 0; j < 4; ++j)
            mv[m * 65 + owner * 4 + j] = cv[rr][j];
    }
    __syncthreads();
    if (t < 128) {
        uint32_t v4[4];
#pragma unroll
        for (int j = 0; j < 4; ++j) v4[j] = 0xFFFFFFFFu;
        const uint32_t* vr = mv + t * 65;
#pragma unroll 4
        for (int j = 0; j < 64; ++j) {
            uint32_t u = vr[j];
            if (u < v4[3]) {
                v4[3] = u;
#pragma unroll
                for (int v = 3; v > 0; --v) {
                    bool sw = v4[v] < v4[v - 1];
                    uint32_t tv = v4[v - 1];
                    v4[v - 1] = sw ? v4[v] : v4[v - 1];
                    v4[v]     = sw ? tv : v4[v];
                }
            }
        }
        int p = b * HW + q0 + t;
        *reinterpret_cast<int4*>(&g_cand[p * 4]) =
            make_int4(v4[0] & 1023, v4[1] & 1023, v4[2] & 1023, v4[3] & 1023);
    }
}

// ---------------------------------------------------------------------------
// Kernel 3: exact fp32 rescore, smem-staged (R13-proven structure), 4 cands.
// A_p from g_A (fp64, proven); d-computation FMA sequence bit-frozen.
// Block = 256 threads; 32 pixels; 4 candidate stages, warp c computes stage c.
// ---------------------------------------------------------------------------
#define RS_ZS   0
#define RS_EB   32768
#define RS_IDS  (RS_EB + 35328)       // int[128]
#define RS_DV   (RS_IDS + 512)        // float[4][32]
#define RS_DI   (RS_DV + 512)         // int[4][32]
#define RS_TOT  (RS_DI + 512)         // 69632 B -> 3 CTAs/SM
#define EPITCH  276                   // floats; 16B-aligned, conflict-free

__global__ __launch_bounds__(256)
void vq_rescore(const float* __restrict__ z, const float* __restrict__ emb,
                float* __restrict__ fo, int* __restrict__ io) {
    float* zs  = reinterpret_cast<float*>(smem + RS_ZS);    // [k][m] pitch 32
    float* ef  = reinterpret_cast<float*>(smem + RS_EB);    // [32][EPITCH]
    int*   ids = reinterpret_cast<int*>(smem + RS_IDS);
    float* dv  = reinterpret_cast<float*>(smem + RS_DV);
    int*   di  = reinterpret_cast<int*>(smem + RS_DI);
    const int t = threadIdx.x, wid = t >> 5, lane = t & 31;
    const int p0 = blockIdx.x * 32;
    const int b = p0 >> 10, q0 = p0 & 1023;
    {
        int m = t & 31, kb = t >> 5;              // identical staging to R12/13
        const float* zb = z + (size_t)b * DIM * HW + q0 + m;
#pragma unroll 8
        for (int i = 0; i < 32; ++i) {
            int k = kb + i * 8;
            zs[k * 32 + m] = zb[(size_t)k * HW];
        }
    }
    if (t < 128) ids[t] = g_cand[p0 * 4 + t];
    __syncthreads();

    const float4* e4g = reinterpret_cast<const float4*>(emb);
    for (int c = 0; c < 4; ++c) {
        {   // coalesced load: 8 threads per row, 32 rows of candidate c
            int r = t >> 3, cc = t & 7;
            const float4* src = e4g + (size_t)ids[r * 4 + c] * 64;
#pragma unroll
            for (int i = 0; i < 8; ++i) {
                float4 v = __ldg(src + cc + i * 8);
                *reinterpret_cast<float4*>(&ef[r * EPITCH + (cc + i * 8) * 4]) = v;
            }
        }
        __syncthreads();
        if (wid == c) {
            const int m = lane, p = p0 + m;
            const int n = ids[m * 4 + c];
            const float Ap = g_A[p], Bn = __ldg(&g_bias[n]);
            const float* er = ef + m * EPITCH;
            const float* zr = zs + m;
            float a0 = 0.f, a1 = 0.f, a2 = 0.f, a3 = 0.f;
#pragma unroll 8
            for (int k4 = 0; k4 < 64; ++k4) {     // bit-frozen serial 4-chain
                float4 e = *reinterpret_cast<const float4*>(&er[k4 * 4]);
                a0 = fmaf(zr[(k4 * 4 + 0) * 32], e.x, a0);
                a1 = fmaf(zr[(k4 * 4 + 1) * 32], e.y, a1);
                a2 = fmaf(zr[(k4 * 4 + 2) * 32], e.z, a2);
                a3 = fmaf(zr[(k4 * 4 + 3) * 32], e.w, a3);
            }
            float dot = (a0 + a1) + (a2 + a3);
            float d = __fadd_rn(__fadd_rn(Ap, Bn), -2.0f * dot);
            dv[c * 32 + m] = d; di[c * 32 + m] = n;
        }
        __syncthreads();   // compute done before ebuf overwritten
    }

    if (t < 32) {          // min over (value, index), lowest index on ties
        float bv = dv[t]; int bi = di[t];
#pragma unroll
        for (int c = 1; c < 4; ++c) {
            float ov = dv[c * 32 + t]; int oi = di[c * 32 + t];
            if (ov < bv || (ov == bv && oi < bi)) { bv = ov; bi = oi; }
        }
        int p = p0 + t;
        g_idx[p] = bi;
        if (fo) fo[p] = (float)bi;
        if (io) io[p] = bi;
    }
}

// ---------------------------------------------------------------------------
// Kernel 4: z_q gather via smem transpose (verbatim, measured 17 us).
// ---------------------------------------------------------------------------
__global__ __launch_bounds__(256)
void vq_gather(const float* __restrict__ emb, float* __restrict__ zq) {
    __shared__ float zsx[32 * 257];
    __shared__ int idx_s[32];
    const int t = threadIdx.x;
    const int p0 = blockIdx.x * 32;
    const int b = p0 >> 10, q0 = p0 & 1023;
    if (t < 32) idx_s[t] = g_idx[p0 + t];
    __syncthreads();
    {
        int r = t >> 3, cc = t & 7;
        const float4* src = reinterpret_cast<const float4*>(emb)
                          + (size_t)idx_s[r] * 64;
#pragma unroll
        for (int i = 0; i < 8; ++i) {
            float4 v = __ldg(src + cc + i * 8);
            int d = (cc + i * 8) * 4;
            zsx[r * 257 + d + 0] = v.x;
            zsx[r * 257 + d + 1] = v.y;
            zsx[r * 257 + d + 2] = v.z;
            zsx[r * 257 + d + 3] = v.w;
        }
    }
    __syncthreads();
    {
        int q = t & 31, w = t >> 5;
        float* o = zq + (size_t)b * DIM * HW + q0 + q;
#pragma unroll 8
        for (int i = 0; i < 32; ++i) {
            int d = w * 32 + i;
            o[(size_t)d * HW] = zsx[q * 257 + d];
        }
    }
}

// ---------------------------------------------------------------------------
extern "C" void kernel_launch(void* const* d_in, const int* in_sizes, int n_in,
                              void* d_out, int out_size) {
    const float* z   = (const float*)d_in[0];
    const float* emb = (const float*)d_in[1];
    if (n_in >= 2 && in_sizes[0] == NCODE * DIM) {
        emb = (const float*)d_in[0]; z = (const float*)d_in[1];
    } else if (n_in >= 2 && in_sizes[1] == NCODE * DIM) {
        z = (const float*)d_in[0]; emb = (const float*)d_in[1];
    }

    const int ZQ = NPIX * DIM;
    float* fo = nullptr; int* io = nullptr; float* zq = nullptr;
    if (out_size == NPIX)      { io = (int*)d_out; }
    else if (out_size == ZQ)   { zq = (float*)d_out; }
    else                       { fo = (float*)d_out; zq = (float*)d_out + NPIX; }

    cudaFuncSetAttribute(vq_gemm, cudaFuncAttributeMaxDynamicSharedMemorySize, SM_TOT);
    cudaFuncSetAttribute(vq_rescore, cudaFuncAttributeMaxDynamicSharedMemorySize, RS_TOT);

    vq_prep<<<128, 256>>>(emb);
    // launch-order padding: makes vq_gemm the 6th launch so ncu (-s 5 -c 1)
    // finally profiles it instead of prep/gather.
    vq_nop<<<1, 32>>>();
    vq_nop<<<1, 32>>>();
    vq_nop<<<1, 32>>>();
    vq_nop<<<1, 32>>>();
    vq_gemm<<<NPIX / 128, 512, SM_TOT>>>(z);
    vq_rescore<<<NPIX / 32, 256, RS_TOT>>>(z, emb, fo, io);
    if (zq) vq_gather<<<NPIX / 32, 256>>>(emb, zq);
}

// round 16
// speedup vs baseline: 1.2724x; 1.0031x over previous
#include <cuda_runtime.h>
#include <cuda_bf16.h>
#include <cstdint>

#define DIM    256
#define HW     1024
#define NPIX   65536
#define NCODE  1024
#define NCHUNK 8          // 1024 codes / 128 per chunk

// ------------------------- device globals (scratch) -------------------------
__device__ float         g_bias[NCODE];        // sum(e_n^2), fp64->fp32
__device__ float         g_A[NPIX];            // sum(z_p^2), compensated fp32
__device__ int           g_cand[NPIX * 4];     // top-4 approx candidates
__device__ int           g_idx[NPIX];          // final indices
__device__ __nv_bfloat16 g_embh[NCODE * DIM];  // bf16 codebook

// ------------------------- PTX helpers (baseline ISA only) ------------------
__device__ __forceinline__ uint32_t smem_u32(const void* p) {
    uint32_t a;
    asm("{ .reg .u64 t; cvta.to.shared.u64 t, %1; cvt.u32.u64 %0, t; }"
        : "=r"(a) : "l"(p));
    return a;
}
__device__ __forceinline__ void ldsm4(uint32_t& r0, uint32_t& r1, uint32_t& r2,
                                      uint32_t& r3, uint32_t addr) {
    asm volatile("ldmatrix.sync.aligned.m8n8.x4.shared.b16 {%0,%1,%2,%3}, [%4];"
                 : "=r"(r0), "=r"(r1), "=r"(r2), "=r"(r3) : "r"(addr));
}
__device__ __forceinline__ void mma16816(float* d, const uint32_t* a,
                                         uint32_t b0, uint32_t b1) {
    asm volatile("mma.sync.aligned.m16n8k16.row.col.f32.bf16.bf16.f32 "
                 "{%0,%1,%2,%3}, {%4,%5,%6,%7}, {%8,%9}, {%0,%1,%2,%3};"
                 : "+f"(d[0]), "+f"(d[1]), "+f"(d[2]), "+f"(d[3])
                 : "r"(a[0]), "r"(a[1]), "r"(a[2]), "r"(a[3]), "r"(b0), "r"(b1));
}
#define CP_ASYNC16(dst, src) \
    asm volatile("cp.async.cg.shared.global [%0], [%1], 16;" :: "r"(dst), "l"(src))
#define CP_COMMIT() asm volatile("cp.async.commit_group;" ::: "memory")
#define CP_WAIT0()  asm volatile("cp.async.wait_group 0;" ::: "memory")

// ---------------------------------------------------------------------------
// Kernel 1 (prep): g_bias (fp64 exact, bit-identical order to prior rounds)
// + bf16 codebook. grid=128, block=256: warp per codebook row.
// ---------------------------------------------------------------------------
__global__ void vq_prep(const float* __restrict__ emb) {
    int n   = blockIdx.x * 8 + (threadIdx.x >> 5);
    int lid = threadIdx.x & 31;
    const float4* row = reinterpret_cast<const float4*>(emb + (size_t)n * DIM);
    float4 u = __ldg(row + lid * 2);
    float4 t = __ldg(row + lid * 2 + 1);
    double s = (double)u.x * u.x + (double)u.y * u.y + (double)u.z * u.z + (double)u.w * u.w
             + (double)t.x * t.x + (double)t.y * t.y + (double)t.z * t.z + (double)t.w * t.w;
#pragma unroll
    for (int off = 16; off; off >>= 1) s += __shfl_xor_sync(0xffffffffu, s, off);
    if (lid == 0) g_bias[n] = (float)s;
    __nv_bfloat162 h0 = __floats2bfloat162_rn(u.x, u.y);
    __nv_bfloat162 h1 = __floats2bfloat162_rn(u.z, u.w);
    __nv_bfloat162 h2 = __floats2bfloat162_rn(t.x, t.y);
    __nv_bfloat162 h3 = __floats2bfloat162_rn(t.z, t.w);
    uint4 o;
    o.x = *reinterpret_cast<uint32_t*>(&h0); o.y = *reinterpret_cast<uint32_t*>(&h1);
    o.z = *reinterpret_cast<uint32_t*>(&h2); o.w = *reinterpret_cast<uint32_t*>(&h3);
    *reinterpret_cast<uint4*>(&g_embh[(size_t)n * DIM + lid * 8]) = o;
}

// ---------------------------------------------------------------------------
// Kernel 2: bf16 mma.sync GEMM + top-4 shortlist (R15 structure). The only
// change vs R15: ||z||^2 uses the R14-PROVEN compensated-fp32 arithmetic
// (Neumaier + FMA residual per 64-elem quarter, TwoSum combine) instead of
// fp64 -- removes the slow DFMA chain from the staging phase.
// ---------------------------------------------------------------------------
#define SM_A   0
#define SM_B0  65536
#define SM_B1  131072
#define SM_SP  196608                 // float[512] quarter sums
#define SM_CP  198656                 // float[512] quarter compensations
#define SM_AF  200704                 // float[128]
#define SM_TOT 201344

#define ROWOFF(row, kc) ((row) * 512 + (((kc) ^ ((row) & 7)) << 4))

__device__ __forceinline__ void prefetch_b(uint32_t bbuf, int nbase, int t) {
    const char* src = (const char*)g_embh + (size_t)nbase * 512;
#pragma unroll
    for (int i = 0; i < 8; ++i) {
        int idx = t + i * 512;       // 0..4095
        int n = idx >> 5, c = idx & 31;
        CP_ASYNC16(bbuf + ROWOFF(n, c), src + n * 512 + c * 16);
    }
}

extern __shared__ char smem[];

__global__ __launch_bounds__(512, 1)
void vq_gemm(const float* __restrict__ z) {
    const uint32_t sb = smem_u32(smem);
    const int t = threadIdx.x, wid = t >> 5, lane = t & 31;
    const int wm = wid & 3, wn = wid >> 2;           // 4 x 4 warp grid
    const int b = blockIdx.x >> 3, q0 = (blockIdx.x & 7) * 128;

    // ---- stage A (fp32 -> bf16, swizzled) + compensated-fp32 ||z||^2 ----
    {
        const int m = t & 127, kq = t >> 7;          // kq 0..3 -> 64 dims each
        const float* zb = z + (size_t)b * DIM * HW + q0 + m;
        float s = 0.f, comp = 0.f, rs = 0.f;         // R14-proven arithmetic
#pragma unroll
        for (int ch = 0; ch < 8; ++ch) {
            int k0 = kq * 64 + ch * 8;
            float vv[8];
#pragma unroll
            for (int j = 0; j < 8; ++j) {
                float v = zb[(size_t)(k0 + j) * HW];
                vv[j] = v;
                float p = v * v;
                float r = fmaf(v, v, -p);            // exact residual
                float tt = s + p;
                comp += (fabsf(s) >= fabsf(p)) ? ((s - tt) + p) : ((p - tt) + s);
                s = tt;
                rs += r;
            }
            uint4 w;
            __nv_bfloat162 h0 = __floats2bfloat162_rn(vv[0], vv[1]);
            __nv_bfloat162 h1 = __floats2bfloat162_rn(vv[2], vv[3]);
            __nv_bfloat162 h2 = __floats2bfloat162_rn(vv[4], vv[5]);
            __nv_bfloat162 h3 = __floats2bfloat162_rn(vv[6], vv[7]);
            w.x = *reinterpret_cast<uint32_t*>(&h0); w.y = *reinterpret_cast<uint32_t*>(&h1);
            w.z = *reinterpret_cast<uint32_t*>(&h2); w.w = *reinterpret_cast<uint32_t*>(&h3);
            *reinterpret_cast<uint4*>(smem + SM_A + ROWOFF(m, k0 >> 3)) = w;
        }
        reinterpret_cast<float*>(smem + SM_SP)[kq * 128 + m] = s;
        reinterpret_cast<float*>(smem + SM_CP)[kq * 128 + m] = comp + rs;
    }

    prefetch_b(sb + SM_B0, 0, t);
    CP_COMMIT();
    CP_WAIT0();
    __syncthreads();

    if (t < 128) {                                   // TwoSum combine (R14 order)
        const float* sp = reinterpret_cast<const float*>(smem + SM_SP);
        const float* cp = reinterpret_cast<const float*>(smem + SM_CP);
        float s = 0.f, c = 0.f;
#pragma unroll
        for (int q = 0; q < 4; ++q) {
            float bq = sp[q * 128 + t];
            float tt = s + bq;
            float bb = tt - s;
            c += (s - (tt - bb)) + (bq - bb);
            s = tt;
            c += cp[q * 128 + t];
        }
        float Af = s + c;
        g_A[b * HW + q0 + t] = Af;
        reinterpret_cast<float*>(smem + SM_AF)[t] = Af;
    }
    __syncthreads();

    const int lrow  = (lane & 7) + ((lane >> 3) & 1) * 8;
    const int kcsel = lane >> 4;
    const int rowA0 = wm * 32 + lrow;
    const int rowB0 = wn * 32 + lrow;
    const uint32_t abase = sb + SM_A;

    float Arow[4];
#pragma unroll
    for (int rr = 0; rr < 4; ++rr) {
        int m = wm * 32 + (rr >> 1) * 16 + (rr & 1) * 8 + (lane >> 2);
        Arow[rr] = reinterpret_cast<const float*>(smem + SM_AF)[m];
    }

    uint32_t cv[4][4];
#pragma unroll
    for (int r = 0; r < 4; ++r)
#pragma unroll
        for (int j = 0; j < 4; ++j) cv[r][j] = 0xFFFFFFFFu;

    for (int nt = 0; nt < NCHUNK; ++nt) {
        if (nt + 1 < NCHUNK) {
            prefetch_b(sb + (((nt + 1) & 1) ? SM_B1 : SM_B0), (nt + 1) * 128, t);
            CP_COMMIT();
        }
        const uint32_t bbuf = sb + ((nt & 1) ? SM_B1 : SM_B0);

        float acc[2][4][4];
#pragma unroll
        for (int mt = 0; mt < 2; ++mt)
#pragma unroll
            for (int n2 = 0; n2 < 4; ++n2)
#pragma unroll
                for (int j = 0; j < 4; ++j) acc[mt][n2][j] = 0.f;

        uint32_t afrag[2][2][4], bfrag[2][2][4];
#define LOAD_KS(ks, buf)                                                        \
        {                                                                       \
            const int kc_ = 2 * (ks) + kcsel;                                   \
            ldsm4(afrag[buf][0][0], afrag[buf][0][1], afrag[buf][0][2],         \
                  afrag[buf][0][3], abase + ROWOFF(rowA0, kc_));                \
            ldsm4(afrag[buf][1][0], afrag[buf][1][1], afrag[buf][1][2],         \
                  afrag[buf][1][3], abase + ROWOFF(rowA0 + 16, kc_));           \
            ldsm4(bfrag[buf][0][0], bfrag[buf][0][1], bfrag[buf][0][2],         \
                  bfrag[buf][0][3], bbuf + ROWOFF(rowB0, kc_));                 \
            ldsm4(bfrag[buf][1][0], bfrag[buf][1][1], bfrag[buf][1][2],         \
                  bfrag[buf][1][3], bbuf + ROWOFF(rowB0 + 16, kc_));            \
        }
        LOAD_KS(0, 0)
#pragma unroll
        for (int ks = 0; ks < 16; ++ks) {
            if (ks < 15) LOAD_KS(ks + 1, (ks + 1) & 1)
            const int cur = ks & 1;
#pragma unroll
            for (int g = 0; g < 2; ++g)
#pragma unroll
                for (int mt = 0; mt < 2; ++mt) {
                    mma16816(acc[mt][g * 2 + 0], afrag[cur][mt],
                             bfrag[cur][g][0], bfrag[cur][g][2]);
                    mma16816(acc[mt][g * 2 + 1], afrag[cur][mt],
                             bfrag[cur][g][1], bfrag[cur][g][3]);
                }
        }
#undef LOAD_KS

        const int nb0 = nt * 128 + wn * 32 + (lane & 3) * 2;
        float bias2[8];
#pragma unroll
        for (int n2 = 0; n2 < 4; ++n2) {
            bias2[n2 * 2 + 0] = __ldg(&g_bias[nb0 + n2 * 8 + 0]);
            bias2[n2 * 2 + 1] = __ldg(&g_bias[nb0 + n2 * 8 + 1]);
        }
#pragma unroll
        for (int mt = 0; mt < 2; ++mt)
#pragma unroll
            for (int h = 0; h < 2; ++h) {
                const int rr = mt * 2 + h;
#pragma unroll
                for (int n2 = 0; n2 < 4; ++n2)
#pragma unroll
                    for (int bb = 0; bb < 2; ++bb) {
                        float s2 = fmaf(-2.f, acc[mt][n2][h * 2 + bb],
                                        bias2[n2 * 2 + bb]) + Arow[rr];
                        uint32_t u = (__float_as_uint(s2) & 0xFFFFFC00u)
                                   | (uint32_t)(nb0 + n2 * 8 + bb);
                        if (u < cv[rr][3]) {
                            cv[rr][3] = u;
#pragma unroll
                            for (int v = 3; v > 0; --v) {
                                bool sw = cv[rr][v] < cv[rr][v - 1];
                                uint32_t tv = cv[rr][v - 1];
                                cv[rr][v - 1] = sw ? cv[rr][v] : cv[rr][v - 1];
                                cv[rr][v]     = sw ? tv : cv[rr][v];
                            }
                        }
                    }
            }

        CP_WAIT0();
        __syncthreads();
    }

    // ---- merge 64 packed candidates/pixel -> top-4 (scratch in B0, pad 65) --
    uint32_t* mv = reinterpret_cast<uint32_t*>(smem + SM_B0);
    const int owner = wn * 4 + (lane & 3);           // 0..15
#pragma unroll
    for (int rr = 0; rr < 4; ++rr) {
        int m = wm * 32 + (rr >> 1) * 16 + (rr & 1) * 8 + (lane >> 2);
#pragma unroll
        for (int j = 0; j < 4; ++j)
            mv[m * 65 + owner * 4 + j] = cv[rr][j];
    }
    __syncthreads();
    if (t < 128) {
        uint32_t v4[4];
#pragma unroll
        for (int j = 0; j < 4; ++j) v4[j] = 0xFFFFFFFFu;
        const uint32_t* vr = mv + t * 65;
#pragma unroll 4
        for (int j = 0; j < 64; ++j) {
            uint32_t u = vr[j];
            if (u < v4[3]) {
                v4[3] = u;
#pragma unroll
                for (int v = 3; v > 0; --v) {
                    bool sw = v4[v] < v4[v - 1];
                    uint32_t tv = v4[v - 1];
                    v4[v - 1] = sw ? v4[v] : v4[v - 1];
                    v4[v]     = sw ? tv : v4[v];
                }
            }
        }
        int p = b * HW + q0 + t;
        *reinterpret_cast<int4*>(&g_cand[p * 4]) =
            make_int4(v4[0] & 1023, v4[1] & 1023, v4[2] & 1023, v4[3] & 1023);
    }
}

// ---------------------------------------------------------------------------
// Kernel 3: exact fp32 rescore, smem-staged (R13/R15-proven), 4 cands.
// d-computation FMA sequence bit-frozen (rounds 2..15 contract).
// ---------------------------------------------------------------------------
#define RS_ZS   0
#define RS_EB   32768
#define RS_IDS  (RS_EB + 35328)       // int[128]
#define RS_DV   (RS_IDS + 512)        // float[4][32]
#define RS_DI   (RS_DV + 512)         // int[4][32]
#define RS_TOT  (RS_DI + 512)         // 69632 B -> 3 CTAs/SM
#define EPITCH  276                   // floats; 16B-aligned, conflict-free

__global__ __launch_bounds__(256)
void vq_rescore(const float* __restrict__ z, const float* __restrict__ emb,
                float* __restrict__ fo, int* __restrict__ io) {
    float* zs  = reinterpret_cast<float*>(smem + RS_ZS);    // [k][m] pitch 32
    float* ef  = reinterpret_cast<float*>(smem + RS_EB);    // [32][EPITCH]
    int*   ids = reinterpret_cast<int*>(smem + RS_IDS);
    float* dv  = reinterpret_cast<float*>(smem + RS_DV);
    int*   di  = reinterpret_cast<int*>(smem + RS_DI);
    const int t = threadIdx.x, wid = t >> 5, lane = t & 31;
    const int p0 = blockIdx.x * 32;
    const int b = p0 >> 10, q0 = p0 & 1023;
    {
        int m = t & 31, kb = t >> 5;
        const float* zb = z + (size_t)b * DIM * HW + q0 + m;
#pragma unroll 8
        for (int i = 0; i < 32; ++i) {
            int k = kb + i * 8;
            zs[k * 32 + m] = zb[(size_t)k * HW];
        }
    }
    if (t < 128) ids[t] = g_cand[p0 * 4 + t];
    __syncthreads();

    const float4* e4g = reinterpret_cast<const float4*>(emb);
    for (int c = 0; c < 4; ++c) {
        {   // coalesced load: 8 threads per row, 32 rows of candidate c
            int r = t >> 3, cc = t & 7;
            const float4* src = e4g + (size_t)ids[r * 4 + c] * 64;
#pragma unroll
            for (int i = 0; i < 8; ++i) {
                float4 v = __ldg(src + cc + i * 8);
                *reinterpret_cast<float4*>(&ef[r * EPITCH + (cc + i * 8) * 4]) = v;
            }
        }
        __syncthreads();
        if (wid == c) {
            const int m = lane, p = p0 + m;
            const int n = ids[m * 4 + c];
            const float Ap = g_A[p], Bn = __ldg(&g_bias[n]);
            const float* er = ef + m * EPITCH;
            const float* zr = zs + m;
            float a0 = 0.f, a1 = 0.f, a2 = 0.f, a3 = 0.f;
#pragma unroll 8
            for (int k4 = 0; k4 < 64; ++k4) {     // bit-frozen serial 4-chain
                float4 e = *reinterpret_cast<const float4*>(&er[k4 * 4]);
                a0 = fmaf(zr[(k4 * 4 + 0) * 32], e.x, a0);
                a1 = fmaf(zr[(k4 * 4 + 1) * 32], e.y, a1);
                a2 = fmaf(zr[(k4 * 4 + 2) * 32], e.z, a2);
                a3 = fmaf(zr[(k4 * 4 + 3) * 32], e.w, a3);
            }
            float dot = (a0 + a1) + (a2 + a3);
            float d = __fadd_rn(__fadd_rn(Ap, Bn), -2.0f * dot);
            dv[c * 32 + m] = d; di[c * 32 + m] = n;
        }
        __syncthreads();   // compute done before ebuf overwritten
    }

    if (t < 32) {          // min over (value, index), lowest index on ties
        float bv = dv[t]; int bi = di[t];
#pragma unroll
        for (int c = 1; c < 4; ++c) {
            float ov = dv[c * 32 + t]; int oi = di[c * 32 + t];
            if (ov < bv || (ov == bv && oi < bi)) { bv = ov; bi = oi; }
        }
        int p = p0 + t;
        g_idx[p] = bi;
        if (fo) fo[p] = (float)bi;
        if (io) io[p] = bi;
    }
}

// ---------------------------------------------------------------------------
// Kernel 4: z_q gather via smem transpose (verbatim, measured 17 us).
// ---------------------------------------------------------------------------
__global__ __launch_bounds__(256)
void vq_gather(const float* __restrict__ emb, float* __restrict__ zq) {
    __shared__ float zsx[32 * 257];
    __shared__ int idx_s[32];
    const int t = threadIdx.x;
    const int p0 = blockIdx.x * 32;
    const int b = p0 >> 10, q0 = p0 & 1023;
    if (t < 32) idx_s[t] = g_idx[p0 + t];
    __syncthreads();
    {
        int r = t >> 3, cc = t & 7;
        const float4* src = reinterpret_cast<const float4*>(emb)
                          + (size_t)idx_s[r] * 64;
#pragma unroll
        for (int i = 0; i < 8; ++i) {
            float4 v = __ldg(src + cc + i * 8);
            int d = (cc + i * 8) * 4;
            zsx[r * 257 + d + 0] = v.x;
            zsx[r * 257 + d + 1] = v.y;
            zsx[r * 257 + d + 2] = v.z;
            zsx[r * 257 + d + 3] = v.w;
        }
    }
    __syncthreads();
    {
        int q = t & 31, w = t >> 5;
        float* o = zq + (size_t)b * DIM * HW + q0 + q;
#pragma unroll 8
        for (int i = 0; i < 32; ++i) {
            int d = w * 32 + i;
            o[(size_t)d * HW] = zsx[q * 257 + d];
        }
    }
}

// ---------------------------------------------------------------------------
extern "C" void kernel_launch(void* const* d_in, const int* in_sizes, int n_in,
                              void* d_out, int out_size) {
    const float* z   = (const float*)d_in[0];
    const float* emb = (const float*)d_in[1];
    if (n_in >= 2 && in_sizes[0] == NCODE * DIM) {
        emb = (const float*)d_in[0]; z = (const float*)d_in[1];
    } else if (n_in >= 2 && in_sizes[1] == NCODE * DIM) {
        z = (const float*)d_in[0]; emb = (const float*)d_in[1];
    }

    const int ZQ = NPIX * DIM;
    float* fo = nullptr; int* io = nullptr; float* zq = nullptr;
    if (out_size == NPIX)      { io = (int*)d_out; }
    else if (out_size == ZQ)   { zq = (float*)d_out; }
    else                       { fo = (float*)d_out; zq = (float*)d_out + NPIX; }

    cudaFuncSetAttribute(vq_gemm, cudaFuncAttributeMaxDynamicSharedMemorySize, SM_TOT);
    cudaFuncSetAttribute(vq_rescore, cudaFuncAttributeMaxDynamicSharedMemorySize, RS_TOT);

    vq_prep<<<128, 256>>>(emb);
    vq_gemm<<<NPIX / 128, 512, SM_TOT>>>(z);
    vq_rescore<<<NPIX / 32, 256, RS_TOT>>>(z, emb, fo, io);
    if (zq) vq_gather<<<NPIX / 32, 256>>>(emb, zq);
}

// round 17
// speedup vs baseline: 1.2725x; 1.0001x over previous
#include <cuda_runtime.h>
#include <cuda_bf16.h>
#include <cstdint>

#define DIM    256
#define HW     1024
#define NPIX   65536
#define NCODE  1024
#define NCHUNK 8          // 1024 codes / 128 per chunk

// ------------------------- device globals (scratch) -------------------------
__device__ float         g_bias[NCODE];        // sum(e_n^2), fp64->fp32
__device__ float         g_A[NPIX];            // sum(z_p^2), compensated fp32
__device__ int           g_cand[NPIX * 4];     // top-4 approx candidates
__device__ int           g_idx[NPIX];          // final indices
__device__ __nv_bfloat16 g_embh[NCODE * DIM];  // bf16 codebook

// ------------------------- PTX helpers (baseline ISA only) ------------------
__device__ __forceinline__ uint32_t smem_u32(const void* p) {
    uint32_t a;
    asm("{ .reg .u64 t; cvta.to.shared.u64 t, %1; cvt.u32.u64 %0, t; }"
        : "=r"(a) : "l"(p));
    return a;
}
__device__ __forceinline__ void ldsm4(uint32_t& r0, uint32_t& r1, uint32_t& r2,
                                      uint32_t& r3, uint32_t addr) {
    asm volatile("ldmatrix.sync.aligned.m8n8.x4.shared.b16 {%0,%1,%2,%3}, [%4];"
                 : "=r"(r0), "=r"(r1), "=r"(r2), "=r"(r3) : "r"(addr));
}
__device__ __forceinline__ void mma16816(float* d, const uint32_t* a,
                                         uint32_t b0, uint32_t b1) {
    asm volatile("mma.sync.aligned.m16n8k16.row.col.f32.bf16.bf16.f32 "
                 "{%0,%1,%2,%3}, {%4,%5,%6,%7}, {%8,%9}, {%0,%1,%2,%3};"
                 : "+f"(d[0]), "+f"(d[1]), "+f"(d[2]), "+f"(d[3])
                 : "r"(a[0]), "r"(a[1]), "r"(a[2]), "r"(a[3]), "r"(b0), "r"(b1));
}
#define CP_ASYNC16(dst, src) \
    asm volatile("cp.async.cg.shared.global [%0], [%1], 16;" :: "r"(dst), "l"(src))
#define CP_COMMIT() asm volatile("cp.async.commit_group;" ::: "memory")
#define CP_WAIT0()  asm volatile("cp.async.wait_group 0;" ::: "memory")

// ---------------------------------------------------------------------------
// Kernel 1 (prep): g_bias (fp64 exact, bit-identical order to prior rounds)
// + bf16 codebook. grid=128, block=256: warp per codebook row.
// ---------------------------------------------------------------------------
__global__ void vq_prep(const float* __restrict__ emb) {
    int n   = blockIdx.x * 8 + (threadIdx.x >> 5);
    int lid = threadIdx.x & 31;
    const float4* row = reinterpret_cast<const float4*>(emb + (size_t)n * DIM);
    float4 u = __ldg(row + lid * 2);
    float4 t = __ldg(row + lid * 2 + 1);
    double s = (double)u.x * u.x + (double)u.y * u.y + (double)u.z * u.z + (double)u.w * u.w
             + (double)t.x * t.x + (double)t.y * t.y + (double)t.z * t.z + (double)t.w * t.w;
#pragma unroll
    for (int off = 16; off; off >>= 1) s += __shfl_xor_sync(0xffffffffu, s, off);
    if (lid == 0) g_bias[n] = (float)s;
    __nv_bfloat162 h0 = __floats2bfloat162_rn(u.x, u.y);
    __nv_bfloat162 h1 = __floats2bfloat162_rn(u.z, u.w);
    __nv_bfloat162 h2 = __floats2bfloat162_rn(t.x, t.y);
    __nv_bfloat162 h3 = __floats2bfloat162_rn(t.z, t.w);
    uint4 o;
    o.x = *reinterpret_cast<uint32_t*>(&h0); o.y = *reinterpret_cast<uint32_t*>(&h1);
    o.z = *reinterpret_cast<uint32_t*>(&h2); o.w = *reinterpret_cast<uint32_t*>(&h3);
    *reinterpret_cast<uint4*>(&g_embh[(size_t)n * DIM + lid * 8]) = o;
}

// ---------------------------------------------------------------------------
// Kernel 2: bf16 mma.sync GEMM + top-4 shortlist. R16 structure with ONE
// change: single-buffered ldsm fragments (register diet, -32 regs) to
// eliminate suspected local-memory spills at the 128-reg/thread cap.
// Latency hiding now relies on 4 warps/SMSP instead of SW pipelining.
// ---------------------------------------------------------------------------
#define SM_A   0
#define SM_B0  65536
#define SM_B1  131072
#define SM_SP  196608                 // float[512] quarter sums
#define SM_CP  198656                 // float[512] quarter compensations
#define SM_AF  200704                 // float[128]
#define SM_TOT 201344

#define ROWOFF(row, kc) ((row) * 512 + (((kc) ^ ((row) & 7)) << 4))

__device__ __forceinline__ void prefetch_b(uint32_t bbuf, int nbase, int t) {
    const char* src = (const char*)g_embh + (size_t)nbase * 512;
#pragma unroll
    for (int i = 0; i < 8; ++i) {
        int idx = t + i * 512;       // 0..4095
        int n = idx >> 5, c = idx & 31;
        CP_ASYNC16(bbuf + ROWOFF(n, c), src + n * 512 + c * 16);
    }
}

extern __shared__ char smem[];

__global__ __launch_bounds__(512, 1)
void vq_gemm(const float* __restrict__ z) {
    const uint32_t sb = smem_u32(smem);
    const int t = threadIdx.x, wid = t >> 5, lane = t & 31;
    const int wm = wid & 3, wn = wid >> 2;           // 4 x 4 warp grid
    const int b = blockIdx.x >> 3, q0 = (blockIdx.x & 7) * 128;

    // ---- stage A (fp32 -> bf16, swizzled) + compensated-fp32 ||z||^2 ----
    {
        const int m = t & 127, kq = t >> 7;          // kq 0..3 -> 64 dims each
        const float* zb = z + (size_t)b * DIM * HW + q0 + m;
        float s = 0.f, comp = 0.f, rs = 0.f;         // R14-proven arithmetic
#pragma unroll
        for (int ch = 0; ch < 8; ++ch) {
            int k0 = kq * 64 + ch * 8;
            float vv[8];
#pragma unroll
            for (int j = 0; j < 8; ++j) {
                float v = zb[(size_t)(k0 + j) * HW];
                vv[j] = v;
                float p = v * v;
                float r = fmaf(v, v, -p);            // exact residual
                float tt = s + p;
                comp += (fabsf(s) >= fabsf(p)) ? ((s - tt) + p) : ((p - tt) + s);
                s = tt;
                rs += r;
            }
            uint4 w;
            __nv_bfloat162 h0 = __floats2bfloat162_rn(vv[0], vv[1]);
            __nv_bfloat162 h1 = __floats2bfloat162_rn(vv[2], vv[3]);
            __nv_bfloat162 h2 = __floats2bfloat162_rn(vv[4], vv[5]);
            __nv_bfloat162 h3 = __floats2bfloat162_rn(vv[6], vv[7]);
            w.x = *reinterpret_cast<uint32_t*>(&h0); w.y = *reinterpret_cast<uint32_t*>(&h1);
            w.z = *reinterpret_cast<uint32_t*>(&h2); w.w = *reinterpret_cast<uint32_t*>(&h3);
            *reinterpret_cast<uint4*>(smem + SM_A + ROWOFF(m, k0 >> 3)) = w;
        }
        reinterpret_cast<float*>(smem + SM_SP)[kq * 128 + m] = s;
        reinterpret_cast<float*>(smem + SM_CP)[kq * 128 + m] = comp + rs;
    }

    prefetch_b(sb + SM_B0, 0, t);
    CP_COMMIT();
    CP_WAIT0();
    __syncthreads();

    if (t < 128) {                                   // TwoSum combine (R14 order)
        const float* sp = reinterpret_cast<const float*>(smem + SM_SP);
        const float* cp = reinterpret_cast<const float*>(smem + SM_CP);
        float s = 0.f, c = 0.f;
#pragma unroll
        for (int q = 0; q < 4; ++q) {
            float bq = sp[q * 128 + t];
            float tt = s + bq;
            float bb = tt - s;
            c += (s - (tt - bb)) + (bq - bb);
            s = tt;
            c += cp[q * 128 + t];
        }
        float Af = s + c;
        g_A[b * HW + q0 + t] = Af;
        reinterpret_cast<float*>(smem + SM_AF)[t] = Af;
    }
    __syncthreads();

    const int lrow  = (lane & 7) + ((lane >> 3) & 1) * 8;
    const int kcsel = lane >> 4;
    const int rowA0 = wm * 32 + lrow;
    const int rowB0 = wn * 32 + lrow;
    const uint32_t abase = sb + SM_A;

    float Arow[4];
#pragma unroll
    for (int rr = 0; rr < 4; ++rr) {
        int m = wm * 32 + (rr >> 1) * 16 + (rr & 1) * 8 + (lane >> 2);
        Arow[rr] = reinterpret_cast<const float*>(smem + SM_AF)[m];
    }

    uint32_t cv[4][4];
#pragma unroll
    for (int r = 0; r < 4; ++r)
#pragma unroll
        for (int j = 0; j < 4; ++j) cv[r][j] = 0xFFFFFFFFu;

    for (int nt = 0; nt < NCHUNK; ++nt) {
        if (nt + 1 < NCHUNK) {
            prefetch_b(sb + (((nt + 1) & 1) ? SM_B1 : SM_B0), (nt + 1) * 128, t);
            CP_COMMIT();
        }
        const uint32_t bbuf = sb + ((nt & 1) ? SM_B1 : SM_B0);

        float acc[2][4][4];
#pragma unroll
        for (int mt = 0; mt < 2; ++mt)
#pragma unroll
            for (int n2 = 0; n2 < 4; ++n2)
#pragma unroll
                for (int j = 0; j < 4; ++j) acc[mt][n2][j] = 0.f;

        // single-buffered fragments (register diet)
#pragma unroll
        for (int ks = 0; ks < 16; ++ks) {
            const int kc = 2 * ks + kcsel;
            uint32_t af[2][4], bf[2][4];
            ldsm4(af[0][0], af[0][1], af[0][2], af[0][3],
                  abase + ROWOFF(rowA0, kc));
            ldsm4(af[1][0], af[1][1], af[1][2], af[1][3],
                  abase + ROWOFF(rowA0 + 16, kc));
            ldsm4(bf[0][0], bf[0][1], bf[0][2], bf[0][3],
                  bbuf + ROWOFF(rowB0, kc));
            ldsm4(bf[1][0], bf[1][1], bf[1][2], bf[1][3],
                  bbuf + ROWOFF(rowB0 + 16, kc));
#pragma unroll
            for (int g = 0; g < 2; ++g)
#pragma unroll
                for (int mt = 0; mt < 2; ++mt) {
                    mma16816(acc[mt][g * 2 + 0], af[mt], bf[g][0], bf[g][2]);
                    mma16816(acc[mt][g * 2 + 1], af[mt], bf[g][1], bf[g][3]);
                }
        }

        const int nb0 = nt * 128 + wn * 32 + (lane & 3) * 2;
        float bias2[8];
#pragma unroll
        for (int n2 = 0; n2 < 4; ++n2) {
            bias2[n2 * 2 + 0] = __ldg(&g_bias[nb0 + n2 * 8 + 0]);
            bias2[n2 * 2 + 1] = __ldg(&g_bias[nb0 + n2 * 8 + 1]);
        }
#pragma unroll
        for (int mt = 0; mt < 2; ++mt)
#pragma unroll
            for (int h = 0; h < 2; ++h) {
                const int rr = mt * 2 + h;
#pragma unroll
                for (int n2 = 0; n2 < 4; ++n2)
#pragma unroll
                    for (int bb = 0; bb < 2; ++bb) {
                        float s2 = fmaf(-2.f, acc[mt][n2][h * 2 + bb],
                                        bias2[n2 * 2 + bb]) + Arow[rr];
                        uint32_t u = (__float_as_uint(s2) & 0xFFFFFC00u)
                                   | (uint32_t)(nb0 + n2 * 8 + bb);
                        if (u < cv[rr][3]) {
                            cv[rr][3] = u;
#pragma unroll
                            for (int v = 3; v > 0; --v) {
                                bool sw = cv[rr][v] < cv[rr][v - 1];
                                uint32_t tv = cv[rr][v - 1];
                                cv[rr][v - 1] = sw ? cv[rr][v] : cv[rr][v - 1];
                                cv[rr][v]     = sw ? tv : cv[rr][v];
                            }
                        }
                    }
            }

        CP_WAIT0();
        __syncthreads();
    }

    // ---- merge 64 packed candidates/pixel -> top-4 (scratch in B0, pad 65) --
    uint32_t* mv = reinterpret_cast<uint32_t*>(smem + SM_B0);
    const int owner = wn * 4 + (lane & 3);           // 0..15
#pragma unroll
    for (int rr = 0; rr < 4; ++rr) {
        int m = wm * 32 + (rr >> 1) * 16 + (rr & 1) * 8 + (lane >> 2);
#pragma unroll
        for (int j = 0; j < 4; ++j)
            mv[m * 65 + owner * 4 + j] = cv[rr][j];
    }
    __syncthreads();
    if (t < 128) {
        uint32_t v4[4];
#pragma unroll
        for (int j = 0; j < 4; ++j) v4[j] = 0xFFFFFFFFu;
        const uint32_t* vr = mv + t * 65;
#pragma unroll 4
        for (int j = 0; j < 64; ++j) {
            uint32_t u = vr[j];
            if (u < v4[3]) {
                v4[3] = u;
#pragma unroll
                for (int v = 3; v > 0; --v) {
                    bool sw = v4[v] < v4[v - 1];
                    uint32_t tv = v4[v - 1];
                    v4[v - 1] = sw ? v4[v] : v4[v - 1];
                    v4[v]     = sw ? tv : v4[v];
                }
            }
        }
        int p = b * HW + q0 + t;
        *reinterpret_cast<int4*>(&g_cand[p * 4]) =
            make_int4(v4[0] & 1023, v4[1] & 1023, v4[2] & 1023, v4[3] & 1023);
    }
}

// ---------------------------------------------------------------------------
// Kernel 3: exact fp32 rescore, smem-staged (R13/R15-proven), 4 cands.
// d-computation FMA sequence bit-frozen (rounds 2..16 contract).
// ---------------------------------------------------------------------------
#define RS_ZS   0
#define RS_EB   32768
#define RS_IDS  (RS_EB + 35328)       // int[128]
#define RS_DV   (RS_IDS + 512)        // float[4][32]
#define RS_DI   (RS_DV + 512)         // int[4][32]
#define RS_TOT  (RS_DI + 512)         // 69632 B -> 3 CTAs/SM
#define EPITCH  276                   // floats; 16B-aligned, conflict-free

__global__ __launch_bounds__(256)
void vq_rescore(const float* __restrict__ z, const float* __restrict__ emb,
                float* __restrict__ fo, int* __restrict__ io) {
    float* zs  = reinterpret_cast<float*>(smem + RS_ZS);    // [k][m] pitch 32
    float* ef  = reinterpret_cast<float*>(smem + RS_EB);    // [32][EPITCH]
    int*   ids = reinterpret_cast<int*>(smem + RS_IDS);
    float* dv  = reinterpret_cast<float*>(smem + RS_DV);
    int*   di  = reinterpret_cast<int*>(smem + RS_DI);
    const int t = threadIdx.x, wid = t >> 5, lane = t & 31;
    const int p0 = blockIdx.x * 32;
    const int b = p0 >> 10, q0 = p0 & 1023;
    {
        int m = t & 31, kb = t >> 5;
        const float* zb = z + (size_t)b * DIM * HW + q0 + m;
#pragma unroll 8
        for (int i = 0; i < 32; ++i) {
            int k = kb + i * 8;
            zs[k * 32 + m] = zb[(size_t)k * HW];
        }
    }
    if (t < 128) ids[t] = g_cand[p0 * 4 + t];
    __syncthreads();

    const float4* e4g = reinterpret_cast<const float4*>(emb);
    for (int c = 0; c < 4; ++c) {
        {   // coalesced load: 8 threads per row, 32 rows of candidate c
            int r = t >> 3, cc = t & 7;
            const float4* src = e4g + (size_t)ids[r * 4 + c] * 64;
#pragma unroll
            for (int i = 0; i < 8; ++i) {
                float4 v = __ldg(src + cc + i * 8);
                *reinterpret_cast<float4*>(&ef[r * EPITCH + (cc + i * 8) * 4]) = v;
            }
        }
        __syncthreads();
        if (wid == c) {
            const int m = lane, p = p0 + m;
            const int n = ids[m * 4 + c];
            const float Ap = g_A[p], Bn = __ldg(&g_bias[n]);
            const float* er = ef + m * EPITCH;
            const float* zr = zs + m;
            float a0 = 0.f, a1 = 0.f, a2 = 0.f, a3 = 0.f;
#pragma unroll 8
            for (int k4 = 0; k4 < 64; ++k4) {     // bit-frozen serial 4-chain
                float4 e = *reinterpret_cast<const float4*>(&er[k4 * 4]);
                a0 = fmaf(zr[(k4 * 4 + 0) * 32], e.x, a0);
                a1 = fmaf(zr[(k4 * 4 + 1) * 32], e.y, a1);
                a2 = fmaf(zr[(k4 * 4 + 2) * 32], e.z, a2);
                a3 = fmaf(zr[(k4 * 4 + 3) * 32], e.w, a3);
            }
            float dot = (a0 + a1) + (a2 + a3);
            float d = __fadd_rn(__fadd_rn(Ap, Bn), -2.0f * dot);
            dv[c * 32 + m] = d; di[c * 32 + m] = n;
        }
        __syncthreads();   // compute done before ebuf overwritten
    }

    if (t < 32) {          // min over (value, index), lowest index on ties
        float bv = dv[t]; int bi = di[t];
#pragma unroll
        for (int c = 1; c < 4; ++c) {
            float ov = dv[c * 32 + t]; int oi = di[c * 32 + t];
            if (ov < bv || (ov == bv && oi < bi)) { bv = ov; bi = oi; }
        }
        int p = p0 + t;
        g_idx[p] = bi;
        if (fo) fo[p] = (float)bi;
        if (io) io[p] = bi;
    }
}

// ---------------------------------------------------------------------------
// Kernel 4: z_q gather via smem transpose (verbatim, measured 17 us).
// ---------------------------------------------------------------------------
__global__ __launch_bounds__(256)
void vq_gather(const float* __restrict__ emb, float* __restrict__ zq) {
    __shared__ float zsx[32 * 257];
    __shared__ int idx_s[32];
    const int t = threadIdx.x;
    const int p0 = blockIdx.x * 32;
    const int b = p0 >> 10, q0 = p0 & 1023;
    if (t < 32) idx_s[t] = g_idx[p0 + t];
    __syncthreads();
    {
        int r = t >> 3, cc = t & 7;
        const float4* src = reinterpret_cast<const float4*>(emb)
                          + (size_t)idx_s[r] * 64;
#pragma unroll
        for (int i = 0; i < 8; ++i) {
            float4 v = __ldg(src + cc + i * 8);
            int d = (cc + i * 8) * 4;
            zsx[r * 257 + d + 0] = v.x;
            zsx[r * 257 + d + 1] = v.y;
            zsx[r * 257 + d + 2] = v.z;
            zsx[r * 257 + d + 3] = v.w;
        }
    }
    __syncthreads();
    {
        int q = t & 31, w = t >> 5;
        float* o = zq + (size_t)b * DIM * HW + q0 + q;
#pragma unroll 8
        for (int i = 0; i < 32; ++i) {
            int d = w * 32 + i;
            o[(size_t)d * HW] = zsx[q * 257 + d];
        }
    }
}

// ---------------------------------------------------------------------------
extern "C" void kernel_launch(void* const* d_in, const int* in_sizes, int n_in,
                              void* d_out, int out_size) {
    const float* z   = (const float*)d_in[0];
    const float* emb = (const float*)d_in[1];
    if (n_in >= 2 && in_sizes[0] == NCODE * DIM) {
        emb = (const float*)d_in[0]; z = (const float*)d_in[1];
    } else if (n_in >= 2 && in_sizes[1] == NCODE * DIM) {
        z = (const float*)d_in[0]; emb = (const float*)d_in[1];
    }

    const int ZQ = NPIX * DIM;
    float* fo = nullptr; int* io = nullptr; float* zq = nullptr;
    if (out_size == NPIX)      { io = (int*)d_out; }
    else if (out_size == ZQ)   { zq = (float*)d_out; }
    else                       { fo = (float*)d_out; zq = (float*)d_out + NPIX; }

    cudaFuncSetAttribute(vq_gemm, cudaFuncAttributeMaxDynamicSharedMemorySize, SM_TOT);
    cudaFuncSetAttribute(vq_rescore, cudaFuncAttributeMaxDynamicSharedMemorySize, RS_TOT);

    vq_prep<<<128, 256>>>(emb);
    vq_gemm<<<NPIX / 128, 512, SM_TOT>>>(z);
    vq_rescore<<<NPIX / 32, 256, RS_TOT>>>(z, emb, fo, io);
    if (zq) vq_gather<<<NPIX / 32, 256>>>(emb, zq);
}